// round 2
// baseline (speedup 1.0000x reference)
#include <cuda_runtime.h>
#include <cstdint>
#include <cstddef>

#define BB    8
#define CIN   128
#define CO    128
#define LIN   2048
#define LOUT  4096
#define CCAT  512
#define DM    256
#define NST   32

// ---------------- device scratch (static: allocation-free) ----------------
__device__ float g_ae[(size_t)BB * CCAT * LIN];   // even-position activations (b,c,l)
__device__ float g_ao[(size_t)BB * CO   * LIN];   // odd-position branch-1 activations
__device__ float g_scale[CCAT];
__device__ float g_shift[CCAT];
__device__ float g_Gw[DM * CCAT];
__device__ float g_Gb[DM];
__device__ float g_Gbodd[DM];
__device__ float g_ue[(size_t)BB * DM * LIN];     // u at even t
__device__ float g_uo[(size_t)BB * DM * LIN];     // u at odd t
__device__ float g_ssm[4 * DM * NST];             // r_re, r_im, 2c_re, 2c_im

// ---------------- K1: fused deconv GEMMs -> raw branch activations ----------------
// seg 0,1 : branch1 tap0 -> ae[c=0..127]    (K=128, no act)
// seg 2..7: branches 2..4 -> ae[c=128..511] (K=256: tap0 @ l, tap1 @ l-d/2, lrelu)
// seg 8,9 : branch1 tap1 -> ao[o=0..127]    (K=128, no act)
__global__ void __launch_bounds__(256) k1_deconv(
    const float* __restrict__ x,
    const float* __restrict__ w1, const float* __restrict__ w2,
    const float* __restrict__ w3, const float* __restrict__ w4,
    const float* __restrict__ b1, const float* __restrict__ b2,
    const float* __restrict__ b3, const float* __restrict__ b4)
{
    __shared__ float Ws[16][68];
    __shared__ float Xs[16][68];
    const int tid = threadIdx.x;
    const int b   = blockIdx.z;
    const int seg = blockIdx.y;
    const int l0  = blockIdx.x * 64;

    const float* wp; const float* bp;
    int KTOT, dj, tapA, c0; bool act, toAo;
    if (seg < 2) {
        wp = w1; bp = b1; KTOT = 128; dj = 0; tapA = 0; act = false; toAo = false; c0 = seg * 64;
    } else if (seg < 8) {
        int j = 1 + ((seg - 2) >> 1);
        wp = (j == 1) ? w2 : ((j == 2) ? w3 : w4);
        bp = (j == 1) ? b2 : ((j == 2) ? b3 : b4);
        KTOT = 256; dj = 1 << (j - 1); tapA = 0; act = true; toAo = false;
        c0 = j * 128 + ((seg - 2) & 1) * 64;
    } else {
        wp = w1; bp = b1; KTOT = 128; dj = 0; tapA = 1; act = false; toAo = true; c0 = (seg - 8) * 64;
    }
    const int obase = c0 & 127;

    float acc[4][4];
#pragma unroll
    for (int i = 0; i < 4; ++i)
#pragma unroll
        for (int j = 0; j < 4; ++j) acc[i][j] = 0.f;

    const int tx = tid & 15, ty = tid >> 4;

    for (int k0 = 0; k0 < KTOT; k0 += 16) {
#pragma unroll
        for (int r = 0; r < 4; ++r) {
            int e  = tid + r * 256;
            int ki = e >> 6, cj = e & 63;
            int k  = k0 + ki;
            int i  = k, tap = tapA;
            if (k >= 128) { i = k - 128; tap = 1; }
            Ws[ki][cj] = wp[(i * 128 + obase + cj) * 2 + tap];
        }
#pragma unroll
        for (int r = 0; r < 4; ++r) {
            int e  = tid + r * 256;
            int ki = e >> 6, lj = e & 63;
            int k  = k0 + ki;
            float v;
            if (k < 128) {
                v = x[((size_t)(b * 128 + k)) * LIN + l0 + lj];
            } else {
                int l = l0 + lj - dj;
                v = (l >= 0) ? x[((size_t)(b * 128 + (k - 128))) * LIN + l] : 0.f;
            }
            Xs[ki][lj] = v;
        }
        __syncthreads();
#pragma unroll
        for (int ki = 0; ki < 16; ++ki) {
            float av[4], bv[4];
#pragma unroll
            for (int i = 0; i < 4; ++i) av[i] = Ws[ki][ty * 4 + i];
#pragma unroll
            for (int j = 0; j < 4; ++j) bv[j] = Xs[ki][tx * 4 + j];
#pragma unroll
            for (int i = 0; i < 4; ++i)
#pragma unroll
                for (int j = 0; j < 4; ++j)
                    acc[i][j] = fmaf(av[i], bv[j], acc[i][j]);
        }
        __syncthreads();
    }

#pragma unroll
    for (int i = 0; i < 4; ++i) {
        int o = obase + ty * 4 + i;
        float bias = bp[o];
        float* outp;
        if (!toAo)
            outp = &g_ae[(((size_t)b * CCAT) + (size_t)(c0 + ty * 4 + i)) * LIN + l0 + tx * 4];
        else
            outp = &g_ao[(((size_t)b * CO) + (size_t)(c0 + ty * 4 + i)) * LIN + l0 + tx * 4];
#pragma unroll
        for (int j = 0; j < 4; ++j) {
            float v = acc[i][j] + bias;
            if (act) v = (v > 0.f) ? v : 0.3f * v;
            outp[j] = v;
        }
    }
}

// ---------------- K2: per-concat-channel batch stats -> BN scale/shift ----------------
__global__ void __launch_bounds__(256) k_stats(
    const float* __restrict__ b2, const float* __restrict__ b3, const float* __restrict__ b4,
    const float* __restrict__ gamma, const float* __restrict__ beta)
{
    const int c = blockIdx.x;            // 0..511
    const int tid = threadIdx.x;
    const int o = c & 127, j = c >> 7;
    float s1 = 0.f, s2 = 0.f;
    const float* ap = g_ae + (size_t)c * LIN;
    for (int idx = tid; idx < BB * LIN; idx += 256) {
        int bb = idx >> 11, l = idx & (LIN - 1);
        float v = ap[(size_t)bb * CCAT * LIN + l];
        s1 += v; s2 += v * v;
    }
    if (j == 0) {
        const float* aop = g_ao + (size_t)c * LIN;
        for (int idx = tid; idx < BB * LIN; idx += 256) {
            int bb = idx >> 11, l = idx & (LIN - 1);
            float v = aop[(size_t)bb * CO * LIN + l];
            s1 += v; s2 += v * v;
        }
    }
    __shared__ float r1[256], r2[256];
    r1[tid] = s1; r2[tid] = s2; __syncthreads();
    for (int s = 128; s > 0; s >>= 1) {
        if (tid < s) { r1[tid] += r1[tid + s]; r2[tid] += r2[tid + s]; }
        __syncthreads();
    }
    if (tid == 0) {
        float S1 = r1[0], S2 = r2[0];
        if (j > 0) {
            const float* bp = (j == 1) ? b2 : ((j == 2) ? b3 : b4);
            float z = bp[o]; z = (z > 0.f) ? z : 0.3f * z;   // odd positions = lrelu(bias)
            S1 += 16384.f * z; S2 += 16384.f * z * z;
        }
        float mean = S1 * (1.f / 32768.f);
        float var  = S2 * (1.f / 32768.f) - mean * mean;
        float sc   = gamma[o] * rsqrtf(var + 1e-5f);
        g_scale[c] = sc;
        g_shift[c] = beta[o] - mean * sc;
    }
}

// ---------------- K3: fold BN into 1x1-conv weights + odd-constant bias ----------------
__global__ void __launch_bounds__(256) k_fold(
    const float* __restrict__ conv_w, const float* __restrict__ conv_b,
    const float* __restrict__ b2, const float* __restrict__ b3, const float* __restrict__ b4)
{
    const int m = blockIdx.x;
    const int tid = threadIdx.x;
    float sAll = 0.f, sOdd = 0.f;
    for (int c = tid; c < CCAT; c += 256) {
        float w  = conv_w[m * CCAT + c];
        float gw = w * g_scale[c];
        g_Gw[m * CCAT + c] = gw;
        sAll += w * g_shift[c];
        if (c >= 128) {
            int j = c >> 7, o = c & 127;
            const float* bp = (j == 1) ? b2 : ((j == 2) ? b3 : b4);
            float z = bp[o]; z = (z > 0.f) ? z : 0.3f * z;
            sOdd += gw * z;
        }
    }
    __shared__ float r1[256], r2[256];
    r1[tid] = sAll; r2[tid] = sOdd; __syncthreads();
    for (int s = 128; s > 0; s >>= 1) {
        if (tid < s) { r1[tid] += r1[tid + s]; r2[tid] += r2[tid + s]; }
        __syncthreads();
    }
    if (tid == 0) {
        float Gb = conv_b[m] + r1[0];
        g_Gb[m] = Gb;
        g_Gbodd[m] = Gb + r2[0];
    }
}

// ---------------- K4: 1x1 conv GEMM (mode 0: even t, K=512; mode 1: odd t, K=128) ----------------
__global__ void __launch_bounds__(256) k_gemm2(int mode)
{
    __shared__ float As[16][68];
    __shared__ float Bs[16][68];
    const int tid = threadIdx.x;
    const int b  = blockIdx.z;
    const int m0 = blockIdx.y * 64;
    const int l0 = blockIdx.x * 64;
    const int tx = tid & 15, ty = tid >> 4;

    const float* Bm = (mode == 0) ? g_ae : g_ao;
    const int K        = (mode == 0) ? 512 : 128;
    const size_t bstrB = (mode == 0) ? (size_t)CCAT * LIN : (size_t)CO * LIN;
    const float* Bb = Bm + (size_t)b * bstrB;

    float acc[4][4];
#pragma unroll
    for (int i = 0; i < 4; ++i)
#pragma unroll
        for (int j = 0; j < 4; ++j) acc[i][j] = 0.f;

    for (int k0 = 0; k0 < K; k0 += 16) {
#pragma unroll
        for (int r = 0; r < 4; ++r) {
            int e  = tid + r * 256;
            int kc = e & 15, mm = e >> 4;
            As[kc][mm] = g_Gw[(m0 + mm) * CCAT + k0 + kc];
        }
#pragma unroll
        for (int r = 0; r < 4; ++r) {
            int e  = tid + r * 256;
            int ki = e >> 6, lj = e & 63;
            Bs[ki][lj] = Bb[((size_t)(k0 + ki)) * LIN + l0 + lj];
        }
        __syncthreads();
#pragma unroll
        for (int ki = 0; ki < 16; ++ki) {
            float av[4], bv[4];
#pragma unroll
            for (int i = 0; i < 4; ++i) av[i] = As[ki][ty * 4 + i];
#pragma unroll
            for (int j = 0; j < 4; ++j) bv[j] = Bs[ki][tx * 4 + j];
#pragma unroll
            for (int i = 0; i < 4; ++i)
#pragma unroll
                for (int j = 0; j < 4; ++j)
                    acc[i][j] = fmaf(av[i], bv[j], acc[i][j]);
        }
        __syncthreads();
    }

    float* out = (mode == 0) ? g_ue : g_uo;
#pragma unroll
    for (int i = 0; i < 4; ++i) {
        int m = m0 + ty * 4 + i;
        float bi = (mode == 0) ? g_Gb[m] : g_Gbodd[m];
        float* op = out + ((size_t)(b * DM + m)) * LIN + l0 + tx * 4;
#pragma unroll
        for (int j = 0; j < 4; ++j) op[j] = acc[i][j] + bi;
    }
}

// ---------------- K5: S4D ZOH discretization per (h, n) ----------------
__global__ void k_s4setup(
    const float* __restrict__ A_re, const float* __restrict__ A_im,
    const float* __restrict__ log_dt,
    const float* __restrict__ C_re, const float* __restrict__ C_im)
{
    const int h = blockIdx.x, n = threadIdx.x;   // 256 x 32
    float dt  = expf(log_dt[h]);
    float ar  = A_re[h * NST + n], ai = A_im[h * NST + n];
    float dre = dt * ar, dim = dt * ai;
    float er  = expf(dre);
    float rre = er * cosf(dim), rim = er * sinf(dim);
    float d2  = ar * ar + ai * ai;
    float nre = rre - 1.f, nim = rim;
    float dbre = (nre * ar + nim * ai) / d2;   // (dA-1)/A
    float dbim = (nim * ar - nre * ai) / d2;
    float cr = C_re[h * NST + n], ci = C_im[h * NST + n];
    float c2re = 2.f * (cr * dbre - ci * dbim);
    float c2im = 2.f * (cr * dbim + ci * dbre);
    int idx = h * NST + n;
    g_ssm[0 * DM * NST + idx] = rre;
    g_ssm[1 * DM * NST + idx] = rim;
    g_ssm[2 * DM * NST + idx] = c2re;
    g_ssm[3 * DM * NST + idx] = c2im;
}

// ---------------- K6: diagonal SSM scan (one warp per (b,h), lane = state) ----------------
__global__ void __launch_bounds__(256) k_scan(const float* __restrict__ Dv, float* __restrict__ out)
{
    const int w = blockIdx.x * 8 + (threadIdx.x >> 5);
    const int lane = threadIdx.x & 31;
    const int b = w >> 8, h = w & 255;
    const int idx = h * NST + lane;
    const float rr   = g_ssm[0 * DM * NST + idx];
    const float ri   = g_ssm[1 * DM * NST + idx];
    const float c2r  = g_ssm[2 * DM * NST + idx];
    const float nc2i = -g_ssm[3 * DM * NST + idx];
    const float nri  = -ri;
    const float Dh   = Dv[h];
    const float* ue = g_ue + ((size_t)(b * DM + h)) * LIN;
    const float* uo = g_uo + ((size_t)(b * DM + h)) * LIN;
    float2* op = (float2*)(out + ((size_t)(b * DM + h)) * LOUT);

    float xr = 0.f, xi = 0.f;
#pragma unroll 2
    for (int l = 0; l < LIN; ++l) {
        float u0 = ue[l], u1 = uo[l];
        // t = 2l
        float t0  = fmaf(nri, xi, u0);
        float xr2 = fmaf(rr, xr, t0);
        float xi2 = fmaf(rr, xi, ri * xr);
        float g0  = fmaf(c2r, xr2, nc2i * xi2);
        // t = 2l+1
        float t1 = fmaf(nri, xi2, u1);
        xr = fmaf(rr, xr2, t1);
        xi = fmaf(rr, xi2, ri * xr2);
        float g1 = fmaf(c2r, xr, nc2i * xi);
#pragma unroll
        for (int o = 16; o > 0; o >>= 1) {
            g0 += __shfl_xor_sync(0xffffffffu, g0, o);
            g1 += __shfl_xor_sync(0xffffffffu, g1, o);
        }
        if (lane == 0) {
            float2 yv;
            yv.x = fmaf(Dh, u0, g0);
            yv.y = fmaf(Dh, u1, g1);
            op[l] = yv;
        }
    }
}

extern "C" void kernel_launch(void* const* d_in, const int* in_sizes, int n_in,
                              void* d_out, int out_size) {
    (void)in_sizes; (void)n_in; (void)out_size;
    const float* x        = (const float*)d_in[0];
    const float* w1       = (const float*)d_in[1];
    const float* b1       = (const float*)d_in[2];
    const float* w2       = (const float*)d_in[3];
    const float* b2       = (const float*)d_in[4];
    const float* w3       = (const float*)d_in[5];
    const float* b3       = (const float*)d_in[6];
    const float* w4       = (const float*)d_in[7];
    const float* b4       = (const float*)d_in[8];
    const float* bn_gamma = (const float*)d_in[9];
    const float* bn_beta  = (const float*)d_in[10];
    const float* conv_w   = (const float*)d_in[11];
    const float* conv_b   = (const float*)d_in[12];
    const float* A_re     = (const float*)d_in[13];
    const float* A_im     = (const float*)d_in[14];
    const float* log_dt   = (const float*)d_in[15];
    const float* C_re     = (const float*)d_in[16];
    const float* C_im     = (const float*)d_in[17];
    const float* Dv       = (const float*)d_in[18];
    float* out = (float*)d_out;

    k1_deconv<<<dim3(LIN / 64, 10, BB), 256>>>(x, w1, w2, w3, w4, b1, b2, b3, b4);
    k_stats<<<CCAT, 256>>>(b2, b3, b4, bn_gamma, bn_beta);
    k_fold<<<DM, 256>>>(conv_w, conv_b, b2, b3, b4);
    k_gemm2<<<dim3(LIN / 64, DM / 64, BB), 256>>>(0);
    k_gemm2<<<dim3(LIN / 64, DM / 64, BB), 256>>>(1);
    k_s4setup<<<DM, NST>>>(A_re, A_im, log_dt, C_re, C_im);
    k_scan<<<(BB * DM) / 8, 256>>>(Dv, out);
}

// round 3
// speedup vs baseline: 1.1102x; 1.1102x over previous
#include <cuda_runtime.h>
#include <cstdint>
#include <cstddef>

#define BB    8
#define CIN   128
#define CO    128
#define LIN   2048
#define LOUT  4096
#define CCAT  512
#define DM    256
#define NST   32

// ---------------- device scratch (static: allocation-free) ----------------
__device__ float g_ae[(size_t)BB * CCAT * LIN];   // even-position activations (b,c,l)
__device__ float g_ao[(size_t)BB * CO   * LIN];   // odd-position branch-1 activations
__device__ float g_scale[CCAT];
__device__ float g_shift[CCAT];
__device__ float g_Gw[DM * CCAT];
__device__ float g_Gb[DM];
__device__ float g_Gbodd[DM];
__device__ float g_ue[(size_t)BB * DM * LIN];     // u at even t
__device__ float g_uo[(size_t)BB * DM * LIN];     // u at odd t
__device__ float g_ssm[4 * DM * NST];             // r_re, r_im, 2c_re, 2c_im

// ---------------- packed f32x2 helpers ----------------
__device__ __forceinline__ unsigned long long pk2(float lo, float hi) {
    unsigned long long r;
    asm("mov.b64 %0, {%1, %2};" : "=l"(r) : "f"(lo), "f"(hi));
    return r;
}
__device__ __forceinline__ unsigned long long dup2(float v) { return pk2(v, v); }
__device__ __forceinline__ void fma2(unsigned long long& d, unsigned long long a, unsigned long long b) {
    asm("fma.rn.f32x2 %0, %1, %2, %0;" : "+l"(d) : "l"(a), "l"(b));
}
__device__ __forceinline__ float2 upk2(unsigned long long v) {
    float2 f;
    asm("mov.b64 {%0, %1}, %2;" : "=f"(f.x), "=f"(f.y) : "l"(v));
    return f;
}

// ---------------- K1: fused deconv GEMMs (128x128 tiles, f32x2) ----------------
// seg 0    : branch1 tap0 -> ae[c=0..127]    (K=128, no act)
// seg 1..3 : branch j+1   -> ae[c=seg*128..] (K=256: tap0 @ l, tap1 @ l-d/2, lrelu)
// seg 4    : branch1 tap1 -> ao[o=0..127]    (K=128, no act)
__global__ void __launch_bounds__(256, 2) k1_deconv(
    const float* __restrict__ x,
    const float* __restrict__ w1, const float* __restrict__ w2,
    const float* __restrict__ w3, const float* __restrict__ w4,
    const float* __restrict__ b1, const float* __restrict__ b2,
    const float* __restrict__ b3, const float* __restrict__ b4)
{
    __shared__ float Ws[16][132];
    __shared__ float Xs[16][132];
    const int tid = threadIdx.x;
    const int b   = blockIdx.z;
    const int seg = blockIdx.y;
    const int l0  = blockIdx.x * 128;

    const float* wp; const float* bp;
    int KTOT, dj, tapA, cbase; bool act, toAo;
    if (seg == 0)      { wp = w1; bp = b1; KTOT = 128; dj = 0; tapA = 0; act = false; toAo = false; cbase = 0; }
    else if (seg <= 3) {
        wp = (seg == 1) ? w2 : ((seg == 2) ? w3 : w4);
        bp = (seg == 1) ? b2 : ((seg == 2) ? b3 : b4);
        KTOT = 256; dj = 1 << (seg - 1); tapA = 0; act = true; toAo = false; cbase = seg * 128;
    } else             { wp = w1; bp = b1; KTOT = 128; dj = 0; tapA = 1; act = false; toAo = true; cbase = 0; }

    const int tx = tid & 15, ty = tid >> 4;

    unsigned long long acc[8][4];
#pragma unroll
    for (int i = 0; i < 8; ++i)
#pragma unroll
        for (int q = 0; q < 4; ++q) acc[i][q] = 0ull;

    for (int k0 = 0; k0 < KTOT; k0 += 16) {
#pragma unroll
        for (int r = 0; r < 8; ++r) {
            int e  = tid + r * 256;
            int ki = e >> 7, o = e & 127;
            int k  = k0 + ki;
            int i  = k, tap = tapA;
            if (k >= 128) { i = k - 128; tap = 1; }
            Ws[ki][o] = wp[(i * 128 + o) * 2 + tap];
        }
#pragma unroll
        for (int r = 0; r < 8; ++r) {
            int e  = tid + r * 256;
            int ki = e >> 7, l = e & 127;
            int k  = k0 + ki;
            float v;
            if (k < 128) {
                v = x[((size_t)(b * 128 + k)) * LIN + l0 + l];
            } else {
                int ll = l0 + l - dj;
                v = (ll >= 0) ? x[((size_t)(b * 128 + (k - 128))) * LIN + ll] : 0.f;
            }
            Xs[ki][l] = v;
        }
        __syncthreads();
#pragma unroll
        for (int ki = 0; ki < 16; ++ki) {
            float4 a0 = *(const float4*)&Ws[ki][ty * 8];
            float4 a1 = *(const float4*)&Ws[ki][ty * 8 + 4];
            float4 v0 = *(const float4*)&Xs[ki][tx * 8];
            float4 v1 = *(const float4*)&Xs[ki][tx * 8 + 4];
            unsigned long long bb[4];
            bb[0] = pk2(v0.x, v0.y); bb[1] = pk2(v0.z, v0.w);
            bb[2] = pk2(v1.x, v1.y); bb[3] = pk2(v1.z, v1.w);
            unsigned long long aa[8];
            aa[0] = dup2(a0.x); aa[1] = dup2(a0.y); aa[2] = dup2(a0.z); aa[3] = dup2(a0.w);
            aa[4] = dup2(a1.x); aa[5] = dup2(a1.y); aa[6] = dup2(a1.z); aa[7] = dup2(a1.w);
#pragma unroll
            for (int i = 0; i < 8; ++i)
#pragma unroll
                for (int q = 0; q < 4; ++q)
                    fma2(acc[i][q], aa[i], bb[q]);
        }
        __syncthreads();
    }

#pragma unroll
    for (int i = 0; i < 8; ++i) {
        int o = ty * 8 + i;
        float bias = bp[o];
        float* outp;
        if (!toAo)
            outp = &g_ae[(((size_t)b * CCAT) + (size_t)(cbase + o)) * LIN + l0 + tx * 8];
        else
            outp = &g_ao[(((size_t)b * CO) + (size_t)o) * LIN + l0 + tx * 8];
        float r[8];
#pragma unroll
        for (int q = 0; q < 4; ++q) {
            float2 f = upk2(acc[i][q]);
            r[2 * q] = f.x + bias; r[2 * q + 1] = f.y + bias;
        }
        if (act) {
#pragma unroll
            for (int q = 0; q < 8; ++q) r[q] = (r[q] > 0.f) ? r[q] : 0.3f * r[q];
        }
        *(float4*)&outp[0] = make_float4(r[0], r[1], r[2], r[3]);
        *(float4*)&outp[4] = make_float4(r[4], r[5], r[6], r[7]);
    }
}

// ---------------- K2: per-concat-channel batch stats -> BN scale/shift ----------------
__global__ void __launch_bounds__(256) k_stats(
    const float* __restrict__ b2, const float* __restrict__ b3, const float* __restrict__ b4,
    const float* __restrict__ gamma, const float* __restrict__ beta)
{
    const int c = blockIdx.x;            // 0..511
    const int tid = threadIdx.x;
    const int o = c & 127, j = c >> 7;
    float s1 = 0.f, s2 = 0.f;
    const float* ap = g_ae + (size_t)c * LIN;
    for (int idx = tid; idx < BB * LIN; idx += 256) {
        int bb = idx >> 11, l = idx & (LIN - 1);
        float v = ap[(size_t)bb * CCAT * LIN + l];
        s1 += v; s2 += v * v;
    }
    if (j == 0) {
        const float* aop = g_ao + (size_t)c * LIN;
        for (int idx = tid; idx < BB * LIN; idx += 256) {
            int bb = idx >> 11, l = idx & (LIN - 1);
            float v = aop[(size_t)bb * CO * LIN + l];
            s1 += v; s2 += v * v;
        }
    }
    __shared__ float r1[256], r2[256];
    r1[tid] = s1; r2[tid] = s2; __syncthreads();
    for (int s = 128; s > 0; s >>= 1) {
        if (tid < s) { r1[tid] += r1[tid + s]; r2[tid] += r2[tid + s]; }
        __syncthreads();
    }
    if (tid == 0) {
        float S1 = r1[0], S2 = r2[0];
        if (j > 0) {
            const float* bp = (j == 1) ? b2 : ((j == 2) ? b3 : b4);
            float z = bp[o]; z = (z > 0.f) ? z : 0.3f * z;   // odd positions = lrelu(bias)
            S1 += 16384.f * z; S2 += 16384.f * z * z;
        }
        float mean = S1 * (1.f / 32768.f);
        float var  = S2 * (1.f / 32768.f) - mean * mean;
        float sc   = gamma[o] * rsqrtf(var + 1e-5f);
        g_scale[c] = sc;
        g_shift[c] = beta[o] - mean * sc;
    }
}

// ---------------- K3: fold BN into 1x1-conv weights + odd-constant bias ----------------
__global__ void __launch_bounds__(256) k_fold(
    const float* __restrict__ conv_w, const float* __restrict__ conv_b,
    const float* __restrict__ b2, const float* __restrict__ b3, const float* __restrict__ b4)
{
    const int m = blockIdx.x;
    const int tid = threadIdx.x;
    float sAll = 0.f, sOdd = 0.f;
    for (int c = tid; c < CCAT; c += 256) {
        float w  = conv_w[m * CCAT + c];
        float gw = w * g_scale[c];
        g_Gw[m * CCAT + c] = gw;
        sAll += w * g_shift[c];
        if (c >= 128) {
            int j = c >> 7, o = c & 127;
            const float* bp = (j == 1) ? b2 : ((j == 2) ? b3 : b4);
            float z = bp[o]; z = (z > 0.f) ? z : 0.3f * z;
            sOdd += gw * z;
        }
    }
    __shared__ float r1[256], r2[256];
    r1[tid] = sAll; r2[tid] = sOdd; __syncthreads();
    for (int s = 128; s > 0; s >>= 1) {
        if (tid < s) { r1[tid] += r1[tid + s]; r2[tid] += r2[tid + s]; }
        __syncthreads();
    }
    if (tid == 0) {
        float Gb = conv_b[m] + r1[0];
        g_Gb[m] = Gb;
        g_Gbodd[m] = Gb + r2[0];
    }
}

// ---------------- K4: 1x1 conv GEMM (128x128 tiles, f32x2) ----------------
// mode 0: even t, K=512, B=g_ae ; mode 1: odd t, K=128, B=g_ao
__global__ void __launch_bounds__(256, 2) k_gemm2(int mode)
{
    __shared__ float As[16][132];
    __shared__ float Bs[16][132];
    const int tid = threadIdx.x;
    const int b  = blockIdx.z;
    const int m0 = blockIdx.y * 128;
    const int l0 = blockIdx.x * 128;
    const int tx = tid & 15, ty = tid >> 4;

    const float* Bm = (mode == 0) ? g_ae : g_ao;
    const int K        = (mode == 0) ? 512 : 128;
    const size_t bstrB = (mode == 0) ? (size_t)CCAT * LIN : (size_t)CO * LIN;
    const float* Bb = Bm + (size_t)b * bstrB;

    unsigned long long acc[8][4];
#pragma unroll
    for (int i = 0; i < 8; ++i)
#pragma unroll
        for (int q = 0; q < 4; ++q) acc[i][q] = 0ull;

    for (int k0 = 0; k0 < K; k0 += 16) {
        // A: [m][k] row-major -> As[k][m], float4 along k
#pragma unroll
        for (int r = 0; r < 2; ++r) {
            int e  = tid + r * 256;
            int mm = e >> 2, kg = (e & 3) * 4;
            float4 a = *(const float4*)&g_Gw[(size_t)(m0 + mm) * CCAT + k0 + kg];
            As[kg + 0][mm] = a.x;
            As[kg + 1][mm] = a.y;
            As[kg + 2][mm] = a.z;
            As[kg + 3][mm] = a.w;
        }
        // B: [k][l] -> Bs[k][l], float4 along l (coalesced)
#pragma unroll
        for (int r = 0; r < 2; ++r) {
            int e  = tid + r * 256;
            int ki = e >> 5, lv = (e & 31) * 4;
            float4 v = *(const float4*)&Bb[((size_t)(k0 + ki)) * LIN + l0 + lv];
            *(float4*)&Bs[ki][lv] = v;
        }
        __syncthreads();
#pragma unroll
        for (int ki = 0; ki < 16; ++ki) {
            float4 a0 = *(const float4*)&As[ki][ty * 8];
            float4 a1 = *(const float4*)&As[ki][ty * 8 + 4];
            float4 v0 = *(const float4*)&Bs[ki][tx * 8];
            float4 v1 = *(const float4*)&Bs[ki][tx * 8 + 4];
            unsigned long long bb[4];
            bb[0] = pk2(v0.x, v0.y); bb[1] = pk2(v0.z, v0.w);
            bb[2] = pk2(v1.x, v1.y); bb[3] = pk2(v1.z, v1.w);
            unsigned long long aa[8];
            aa[0] = dup2(a0.x); aa[1] = dup2(a0.y); aa[2] = dup2(a0.z); aa[3] = dup2(a0.w);
            aa[4] = dup2(a1.x); aa[5] = dup2(a1.y); aa[6] = dup2(a1.z); aa[7] = dup2(a1.w);
#pragma unroll
            for (int i = 0; i < 8; ++i)
#pragma unroll
                for (int q = 0; q < 4; ++q)
                    fma2(acc[i][q], aa[i], bb[q]);
        }
        __syncthreads();
    }

    float* out = (mode == 0) ? g_ue : g_uo;
#pragma unroll
    for (int i = 0; i < 8; ++i) {
        int m = m0 + ty * 8 + i;
        float bi = (mode == 0) ? g_Gb[m] : g_Gbodd[m];
        float* op = out + ((size_t)(b * DM + m)) * LIN + l0 + tx * 8;
        float r[8];
#pragma unroll
        for (int q = 0; q < 4; ++q) {
            float2 f = upk2(acc[i][q]);
            r[2 * q] = f.x + bi; r[2 * q + 1] = f.y + bi;
        }
        *(float4*)&op[0] = make_float4(r[0], r[1], r[2], r[3]);
        *(float4*)&op[4] = make_float4(r[4], r[5], r[6], r[7]);
    }
}

// ---------------- K5: S4D ZOH discretization per (h, n) ----------------
__global__ void k_s4setup(
    const float* __restrict__ A_re, const float* __restrict__ A_im,
    const float* __restrict__ log_dt,
    const float* __restrict__ C_re, const float* __restrict__ C_im)
{
    const int h = blockIdx.x, n = threadIdx.x;   // 256 x 32
    float dt  = expf(log_dt[h]);
    float ar  = A_re[h * NST + n], ai = A_im[h * NST + n];
    float dre = dt * ar, dim = dt * ai;
    float er  = expf(dre);
    float rre = er * cosf(dim), rim = er * sinf(dim);
    float d2  = ar * ar + ai * ai;
    float nre = rre - 1.f, nim = rim;
    float dbre = (nre * ar + nim * ai) / d2;   // (dA-1)/A
    float dbim = (nim * ar - nre * ai) / d2;
    float cr = C_re[h * NST + n], ci = C_im[h * NST + n];
    float c2re = 2.f * (cr * dbre - ci * dbim);
    float c2im = 2.f * (cr * dbim + ci * dbre);
    int idx = h * NST + n;
    g_ssm[0 * DM * NST + idx] = rre;
    g_ssm[1 * DM * NST + idx] = rim;
    g_ssm[2 * DM * NST + idx] = c2re;
    g_ssm[3 * DM * NST + idx] = c2im;
}

// ---------------- K6: diagonal SSM scan (one warp per (b,h), lane = state) ----------------
__global__ void __launch_bounds__(256) k_scan(const float* __restrict__ Dv, float* __restrict__ out)
{
    const int w = blockIdx.x * 8 + (threadIdx.x >> 5);
    const int lane = threadIdx.x & 31;
    const int b = w >> 8, h = w & 255;
    const int idx = h * NST + lane;
    const float rr   = g_ssm[0 * DM * NST + idx];
    const float ri   = g_ssm[1 * DM * NST + idx];
    const float c2r  = g_ssm[2 * DM * NST + idx];
    const float nc2i = -g_ssm[3 * DM * NST + idx];
    const float nri  = -ri;
    const float Dh   = Dv[h];
    const float* ue = g_ue + ((size_t)(b * DM + h)) * LIN;
    const float* uo = g_uo + ((size_t)(b * DM + h)) * LIN;
    float2* op = (float2*)(out + ((size_t)(b * DM + h)) * LOUT);

    float xr = 0.f, xi = 0.f;
#pragma unroll 2
    for (int l = 0; l < LIN; ++l) {
        float u0 = __ldg(&ue[l]), u1 = __ldg(&uo[l]);
        // t = 2l
        float t0  = fmaf(nri, xi, u0);
        float xr2 = fmaf(rr, xr, t0);
        float xi2 = fmaf(rr, xi, ri * xr);
        float g0  = fmaf(c2r, xr2, nc2i * xi2);
        // t = 2l+1
        float t1 = fmaf(nri, xi2, u1);
        xr = fmaf(rr, xr2, t1);
        xi = fmaf(rr, xi2, ri * xr2);
        float g1 = fmaf(c2r, xr, nc2i * xi);
#pragma unroll
        for (int o = 16; o > 0; o >>= 1) {
            g0 += __shfl_xor_sync(0xffffffffu, g0, o);
            g1 += __shfl_xor_sync(0xffffffffu, g1, o);
        }
        if (lane == 0) {
            float2 yv;
            yv.x = fmaf(Dh, u0, g0);
            yv.y = fmaf(Dh, u1, g1);
            op[l] = yv;
        }
    }
}

extern "C" void kernel_launch(void* const* d_in, const int* in_sizes, int n_in,
                              void* d_out, int out_size) {
    (void)in_sizes; (void)n_in; (void)out_size;
    const float* x        = (const float*)d_in[0];
    const float* w1       = (const float*)d_in[1];
    const float* b1       = (const float*)d_in[2];
    const float* w2       = (const float*)d_in[3];
    const float* b2       = (const float*)d_in[4];
    const float* w3       = (const float*)d_in[5];
    const float* b3       = (const float*)d_in[6];
    const float* w4       = (const float*)d_in[7];
    const float* b4       = (const float*)d_in[8];
    const float* bn_gamma = (const float*)d_in[9];
    const float* bn_beta  = (const float*)d_in[10];
    const float* conv_w   = (const float*)d_in[11];
    const float* conv_b   = (const float*)d_in[12];
    const float* A_re     = (const float*)d_in[13];
    const float* A_im     = (const float*)d_in[14];
    const float* log_dt   = (const float*)d_in[15];
    const float* C_re     = (const float*)d_in[16];
    const float* C_im     = (const float*)d_in[17];
    const float* Dv       = (const float*)d_in[18];
    float* out = (float*)d_out;

    k1_deconv<<<dim3(LIN / 128, 5, BB), 256>>>(x, w1, w2, w3, w4, b1, b2, b3, b4);
    k_stats<<<CCAT, 256>>>(b2, b3, b4, bn_gamma, bn_beta);
    k_fold<<<DM, 256>>>(conv_w, conv_b, b2, b3, b4);
    k_gemm2<<<dim3(LIN / 128, DM / 128, BB), 256>>>(0);
    k_gemm2<<<dim3(LIN / 128, DM / 128, BB), 256>>>(1);
    k_s4setup<<<DM, NST>>>(A_re, A_im, log_dt, C_re, C_im);
    k_scan<<<(BB * DM) / 8, 256>>>(Dv, out);
}

// round 5
// speedup vs baseline: 1.6240x; 1.4629x over previous
#include <cuda_runtime.h>
#include <cstdint>
#include <cstddef>

#define BB    8
#define CIN   128
#define CO    128
#define LIN   2048
#define LOUT  4096
#define CCAT  512
#define DM    256
#define NST   32

// ---------------- device scratch (static: allocation-free) ----------------
__device__ float g_ae[(size_t)BB * CCAT * LIN];   // even-position activations (b,c,l)
__device__ float g_ao[(size_t)BB * CO   * LIN];   // odd-position branch-1 activations
__device__ float g_scale[CCAT];
__device__ float g_shift[CCAT];
__device__ float g_GwT[CCAT * DM];                // folded 1x1 weights, transposed [c][m]
__device__ float g_Gb[DM];
__device__ float g_Gbodd[DM];
__device__ float g_ue[(size_t)BB * DM * LIN];     // u at even t
__device__ float g_uo[(size_t)BB * DM * LIN];     // u at odd t
__device__ float g_ssm[4 * DM * NST];             // r_re, r_im, 2c_re, 2c_im
__device__ float g_wk[8 * 128 * 128];             // packed deconv weights, 8 planes [ch][o]

// ---------------- packed f32x2 helpers ----------------
__device__ __forceinline__ unsigned long long pk2(float lo, float hi) {
    unsigned long long r;
    asm("mov.b64 %0, {%1, %2};" : "=l"(r) : "f"(lo), "f"(hi));
    return r;
}
__device__ __forceinline__ unsigned long long dup2(float v) { return pk2(v, v); }
__device__ __forceinline__ void fma2(unsigned long long& d, unsigned long long a, unsigned long long b) {
    asm("fma.rn.f32x2 %0, %1, %2, %0;" : "+l"(d) : "l"(a), "l"(b));
}
__device__ __forceinline__ float2 upk2(unsigned long long v) {
    float2 f;
    asm("mov.b64 {%0, %1}, %2;" : "=f"(f.x), "=f"(f.y) : "l"(v));
    return f;
}

// ---------------- cp.async helpers ----------------
__device__ __forceinline__ void cpa16(void* dst, const void* src) {
    unsigned ds = (unsigned)__cvta_generic_to_shared(dst);
    asm volatile("cp.async.cg.shared.global [%0], [%1], 16;" :: "r"(ds), "l"(src));
}
__device__ __forceinline__ void cpa_commit() { asm volatile("cp.async.commit_group;"); }
__device__ __forceinline__ void cpa_wait1()  { asm volatile("cp.async.wait_group 1;"); }

// ---------------- K0: pack deconv weights into contiguous planes ----------------
// plane: 0=w1t0 1=w2t0 2=w2t1 3=w3t0 4=w3t1 5=w4t0 6=w4t1 7=w1t1
__global__ void k_wprep(const float* __restrict__ w1, const float* __restrict__ w2,
                        const float* __restrict__ w3, const float* __restrict__ w4)
{
    int idx = blockIdx.x * 256 + threadIdx.x;     // 0 .. 8*16384-1
    int plane = idx >> 14;
    int r = idx & 16383;
    const float* w; int tap;
    switch (plane) {
        case 0: w = w1; tap = 0; break;
        case 1: w = w2; tap = 0; break;
        case 2: w = w2; tap = 1; break;
        case 3: w = w3; tap = 0; break;
        case 4: w = w3; tap = 1; break;
        case 5: w = w4; tap = 0; break;
        case 6: w = w4; tap = 1; break;
        default: w = w1; tap = 1; break;
    }
    g_wk[idx] = w[r * 2 + tap];
}

// ---------------- K1: fused deconv GEMMs (cp.async double-buffered) ----------------
__global__ void __launch_bounds__(256, 2) k1_deconv(
    const float* __restrict__ x,
    const float* __restrict__ b1, const float* __restrict__ b2,
    const float* __restrict__ b3, const float* __restrict__ b4)
{
    __shared__ float Xs[2][8][132];
    __shared__ float W0s[2][8][128];
    __shared__ float W1s[2][8][128];

    const int tid = threadIdx.x;
    const int b   = blockIdx.z;
    const int seg = blockIdx.y;
    const int l0  = blockIdx.x * 128;
    const int tx = tid & 15, ty = tid >> 4;

    int p0, p1, dj, cbase; bool act, toAo;
    const float* bp;
    switch (seg) {
        case 0:  p0 = 0; p1 = -1; dj = 0; act = false; toAo = false; cbase = 0;   bp = b1; break;
        case 1:  p0 = 1; p1 = 2;  dj = 1; act = true;  toAo = false; cbase = 128; bp = b2; break;
        case 2:  p0 = 3; p1 = 4;  dj = 2; act = true;  toAo = false; cbase = 256; bp = b3; break;
        case 3:  p0 = 5; p1 = 6;  dj = 4; act = true;  toAo = false; cbase = 384; bp = b4; break;
        default: p0 = 7; p1 = -1; dj = 0; act = false; toAo = true;  cbase = 0;   bp = b1; break;
    }
    const bool dual = (p1 >= 0);
    const float* xb = x + (size_t)b * 128 * LIN;

    unsigned long long acc[8][4];
#pragma unroll
    for (int i = 0; i < 8; ++i)
#pragma unroll
        for (int q = 0; q < 4; ++q) acc[i][q] = 0ull;

    auto issue = [&](int ch) {
        const int buf = ch & 1;
        const int c0  = ch * 8;
        for (int e = tid; e < 264; e += 256) {
            int row = e / 33;
            int q   = e - row * 33;
            float* dst = &Xs[buf][row][q * 4];
            if (l0 == 0 && q == 0) {
                *(float4*)dst = make_float4(0.f, 0.f, 0.f, 0.f);
            } else {
                cpa16(dst, &xb[(size_t)(c0 + row) * LIN + l0 - 4 + q * 4]);
            }
        }
        {
            int row = tid >> 5, q = tid & 31;
            cpa16(&W0s[buf][row][q * 4], &g_wk[(size_t)p0 * 16384 + (c0 + row) * 128 + q * 4]);
            if (dual)
                cpa16(&W1s[buf][row][q * 4], &g_wk[(size_t)p1 * 16384 + (c0 + row) * 128 + q * 4]);
        }
    };

    issue(0); cpa_commit();
    const int NCH = 16;
    for (int ch = 0; ch < NCH; ++ch) {
        if (ch + 1 < NCH) issue(ch + 1);
        cpa_commit();
        cpa_wait1();
        __syncthreads();
        const int buf = ch & 1;
#pragma unroll
        for (int ki = 0; ki < 8; ++ki) {
            float4 v0 = *(const float4*)&Xs[buf][ki][4 + tx * 8];
            float4 v1 = *(const float4*)&Xs[buf][ki][8 + tx * 8];
            float4 a0 = *(const float4*)&W0s[buf][ki][ty * 8];
            float4 a1 = *(const float4*)&W0s[buf][ki][ty * 8 + 4];
            unsigned long long bb[4];
            bb[0] = pk2(v0.x, v0.y); bb[1] = pk2(v0.z, v0.w);
            bb[2] = pk2(v1.x, v1.y); bb[3] = pk2(v1.z, v1.w);
            unsigned long long aa[8];
            aa[0] = dup2(a0.x); aa[1] = dup2(a0.y); aa[2] = dup2(a0.z); aa[3] = dup2(a0.w);
            aa[4] = dup2(a1.x); aa[5] = dup2(a1.y); aa[6] = dup2(a1.z); aa[7] = dup2(a1.w);
#pragma unroll
            for (int i = 0; i < 8; ++i)
#pragma unroll
                for (int q = 0; q < 4; ++q)
                    fma2(acc[i][q], aa[i], bb[q]);

            if (dual) {
                float xv[8];
                if (dj == 4) {
                    float4 u0 = *(const float4*)&Xs[buf][ki][tx * 8];
                    float4 u1 = *(const float4*)&Xs[buf][ki][tx * 8 + 4];
                    xv[0] = u0.x; xv[1] = u0.y; xv[2] = u0.z; xv[3] = u0.w;
                    xv[4] = u1.x; xv[5] = u1.y; xv[6] = u1.z; xv[7] = u1.w;
                } else {
                    int off = 4 - dj + tx * 8;
#pragma unroll
                    for (int q = 0; q < 8; ++q) xv[q] = Xs[buf][ki][off + q];
                }
                float4 c0v = *(const float4*)&W1s[buf][ki][ty * 8];
                float4 c1v = *(const float4*)&W1s[buf][ki][ty * 8 + 4];
                unsigned long long bb2[4];
                bb2[0] = pk2(xv[0], xv[1]); bb2[1] = pk2(xv[2], xv[3]);
                bb2[2] = pk2(xv[4], xv[5]); bb2[3] = pk2(xv[6], xv[7]);
                unsigned long long aa2[8];
                aa2[0] = dup2(c0v.x); aa2[1] = dup2(c0v.y); aa2[2] = dup2(c0v.z); aa2[3] = dup2(c0v.w);
                aa2[4] = dup2(c1v.x); aa2[5] = dup2(c1v.y); aa2[6] = dup2(c1v.z); aa2[7] = dup2(c1v.w);
#pragma unroll
                for (int i = 0; i < 8; ++i)
#pragma unroll
                    for (int q = 0; q < 4; ++q)
                        fma2(acc[i][q], aa2[i], bb2[q]);
            }
        }
        __syncthreads();
    }

#pragma unroll
    for (int i = 0; i < 8; ++i) {
        int o = ty * 8 + i;
        float bias = bp[o];
        float* outp;
        if (!toAo)
            outp = &g_ae[(((size_t)b * CCAT) + (size_t)(cbase + o)) * LIN + l0 + tx * 8];
        else
            outp = &g_ao[(((size_t)b * CO) + (size_t)o) * LIN + l0 + tx * 8];
        float r[8];
#pragma unroll
        for (int q = 0; q < 4; ++q) {
            float2 f = upk2(acc[i][q]);
            r[2 * q] = f.x + bias; r[2 * q + 1] = f.y + bias;
        }
        if (act) {
#pragma unroll
            for (int q = 0; q < 8; ++q) r[q] = (r[q] > 0.f) ? r[q] : 0.3f * r[q];
        }
        *(float4*)&outp[0] = make_float4(r[0], r[1], r[2], r[3]);
        *(float4*)&outp[4] = make_float4(r[4], r[5], r[6], r[7]);
    }
}

// ---------------- K2: per-concat-channel batch stats -> BN scale/shift ----------------
__global__ void __launch_bounds__(256) k_stats(
    const float* __restrict__ b2, const float* __restrict__ b3, const float* __restrict__ b4,
    const float* __restrict__ gamma, const float* __restrict__ beta)
{
    const int c = blockIdx.x;            // 0..511
    const int tid = threadIdx.x;
    const int o = c & 127, j = c >> 7;
    float s1 = 0.f, s2 = 0.f;
    const float* ap = g_ae + (size_t)c * LIN;
    for (int idx = tid; idx < BB * LIN; idx += 256) {
        int bb = idx >> 11, l = idx & (LIN - 1);
        float v = ap[(size_t)bb * CCAT * LIN + l];
        s1 += v; s2 += v * v;
    }
    if (j == 0) {
        const float* aop = g_ao + (size_t)c * LIN;
        for (int idx = tid; idx < BB * LIN; idx += 256) {
            int bb = idx >> 11, l = idx & (LIN - 1);
            float v = aop[(size_t)bb * CO * LIN + l];
            s1 += v; s2 += v * v;
        }
    }
    __shared__ float r1[256], r2[256];
    r1[tid] = s1; r2[tid] = s2; __syncthreads();
    for (int s = 128; s > 0; s >>= 1) {
        if (tid < s) { r1[tid] += r1[tid + s]; r2[tid] += r2[tid + s]; }
        __syncthreads();
    }
    if (tid == 0) {
        float S1 = r1[0], S2 = r2[0];
        if (j > 0) {
            const float* bp = (j == 1) ? b2 : ((j == 2) ? b3 : b4);
            float z = bp[o]; z = (z > 0.f) ? z : 0.3f * z;   // odd positions = lrelu(bias)
            S1 += 16384.f * z; S2 += 16384.f * z * z;
        }
        float mean = S1 * (1.f / 32768.f);
        float var  = S2 * (1.f / 32768.f) - mean * mean;
        float sc   = gamma[o] * rsqrtf(var + 1e-5f);
        g_scale[c] = sc;
        g_shift[c] = beta[o] - mean * sc;
    }
}

// ---------------- K3: fold BN into 1x1-conv weights (transposed) + biases ----------------
__global__ void __launch_bounds__(256) k_fold(
    const float* __restrict__ conv_w, const float* __restrict__ conv_b,
    const float* __restrict__ b2, const float* __restrict__ b3, const float* __restrict__ b4)
{
    const int m = blockIdx.x;
    const int tid = threadIdx.x;
    float sAll = 0.f, sOdd = 0.f;
    for (int c = tid; c < CCAT; c += 256) {
        float w  = conv_w[m * CCAT + c];
        float gw = w * g_scale[c];
        g_GwT[c * DM + m] = gw;
        sAll += w * g_shift[c];
        if (c >= 128) {
            int j = c >> 7, o = c & 127;
            const float* bp = (j == 1) ? b2 : ((j == 2) ? b3 : b4);
            float z = bp[o]; z = (z > 0.f) ? z : 0.3f * z;
            sOdd += gw * z;
        }
    }
    __shared__ float r1[256], r2[256];
    r1[tid] = sAll; r2[tid] = sOdd; __syncthreads();
    for (int s = 128; s > 0; s >>= 1) {
        if (tid < s) { r1[tid] += r1[tid + s]; r2[tid] += r2[tid + s]; }
        __syncthreads();
    }
    if (tid == 0) {
        float Gb = conv_b[m] + r1[0];
        g_Gb[m] = Gb;
        g_Gbodd[m] = Gb + r2[0];
    }
}

// ---------------- K4: 1x1 conv GEMM (cp.async double-buffered, f32x2) ----------------
__global__ void __launch_bounds__(256, 2) k_gemm2(int mode)
{
    __shared__ float As[2][16][128];
    __shared__ float Bs[2][16][128];
    const int tid = threadIdx.x;
    const int b  = blockIdx.z;
    const int m0 = blockIdx.y * 128;
    const int l0 = blockIdx.x * 128;
    const int tx = tid & 15, ty = tid >> 4;

    const float* Bm = (mode == 0) ? g_ae : g_ao;
    const int K        = (mode == 0) ? 512 : 128;
    const size_t bstrB = (mode == 0) ? (size_t)CCAT * LIN : (size_t)CO * LIN;
    const float* Bb = Bm + (size_t)b * bstrB;

    unsigned long long acc[8][4];
#pragma unroll
    for (int i = 0; i < 8; ++i)
#pragma unroll
        for (int q = 0; q < 4; ++q) acc[i][q] = 0ull;

    auto issue = [&](int ch) {
        const int buf = ch & 1;
        const int k0  = ch * 16;
#pragma unroll
        for (int r = 0; r < 2; ++r) {
            int e = tid + r * 256;
            int row = e >> 5, q = e & 31;
            cpa16(&As[buf][row][q * 4], &g_GwT[(size_t)(k0 + row) * DM + m0 + q * 4]);
        }
#pragma unroll
        for (int r = 0; r < 2; ++r) {
            int e = tid + r * 256;
            int row = e >> 5, q = e & 31;
            cpa16(&Bs[buf][row][q * 4], &Bb[(size_t)(k0 + row) * LIN + l0 + q * 4]);
        }
    };

    issue(0); cpa_commit();
    const int NCH = K / 16;
    for (int ch = 0; ch < NCH; ++ch) {
        if (ch + 1 < NCH) issue(ch + 1);
        cpa_commit();
        cpa_wait1();
        __syncthreads();
        const int buf = ch & 1;
#pragma unroll
        for (int ki = 0; ki < 16; ++ki) {
            float4 a0 = *(const float4*)&As[buf][ki][ty * 8];
            float4 a1 = *(const float4*)&As[buf][ki][ty * 8 + 4];
            float4 v0 = *(const float4*)&Bs[buf][ki][tx * 8];
            float4 v1 = *(const float4*)&Bs[buf][ki][tx * 8 + 4];
            unsigned long long bb[4];
            bb[0] = pk2(v0.x, v0.y); bb[1] = pk2(v0.z, v0.w);
            bb[2] = pk2(v1.x, v1.y); bb[3] = pk2(v1.z, v1.w);
            unsigned long long aa[8];
            aa[0] = dup2(a0.x); aa[1] = dup2(a0.y); aa[2] = dup2(a0.z); aa[3] = dup2(a0.w);
            aa[4] = dup2(a1.x); aa[5] = dup2(a1.y); aa[6] = dup2(a1.z); aa[7] = dup2(a1.w);
#pragma unroll
            for (int i = 0; i < 8; ++i)
#pragma unroll
                for (int q = 0; q < 4; ++q)
                    fma2(acc[i][q], aa[i], bb[q]);
        }
        __syncthreads();
    }

    float* out = (mode == 0) ? g_ue : g_uo;
#pragma unroll
    for (int i = 0; i < 8; ++i) {
        int m = m0 + ty * 8 + i;
        float bi = (mode == 0) ? g_Gb[m] : g_Gbodd[m];
        float* op = out + ((size_t)(b * DM + m)) * LIN + l0 + tx * 8;
        float r[8];
#pragma unroll
        for (int q = 0; q < 4; ++q) {
            float2 f = upk2(acc[i][q]);
            r[2 * q] = f.x + bi; r[2 * q + 1] = f.y + bi;
        }
        *(float4*)&op[0] = make_float4(r[0], r[1], r[2], r[3]);
        *(float4*)&op[4] = make_float4(r[4], r[5], r[6], r[7]);
    }
}

// ---------------- K5: S4D ZOH discretization per (h, n) ----------------
__global__ void k_s4setup(
    const float* __restrict__ A_re, const float* __restrict__ A_im,
    const float* __restrict__ log_dt,
    const float* __restrict__ C_re, const float* __restrict__ C_im)
{
    const int h = blockIdx.x, n = threadIdx.x;   // 256 x 32
    float dt  = expf(log_dt[h]);
    float ar  = A_re[h * NST + n], ai = A_im[h * NST + n];
    float dre = dt * ar, dim = dt * ai;
    float er  = expf(dre);
    float rre = er * cosf(dim), rim = er * sinf(dim);
    float d2  = ar * ar + ai * ai;
    float nre = rre - 1.f, nim = rim;
    float dbre = (nre * ar + nim * ai) / d2;   // (dA-1)/A
    float dbim = (nim * ar - nre * ai) / d2;
    float cr = C_re[h * NST + n], ci = C_im[h * NST + n];
    float c2re = 2.f * (cr * dbre - ci * dbim);
    float c2im = 2.f * (cr * dbim + ci * dbre);
    int idx = h * NST + n;
    g_ssm[0 * DM * NST + idx] = rre;
    g_ssm[1 * DM * NST + idx] = rim;
    g_ssm[2 * DM * NST + idx] = c2re;
    g_ssm[3 * DM * NST + idx] = c2im;
}

// ---------------- K6: diagonal SSM scan, chunked smem-transpose reduction ----------------
// one warp per (b,h); lane = state. Each lane accumulates 16 even + 16 odd outputs
// in registers, then a [32][33]-padded transpose turns the cross-state sum into
// stride-1 LDS. Even cols 0..15, odd cols 16..31.
__global__ void __launch_bounds__(256) k_scan(const float* __restrict__ Dv, float* __restrict__ out)
{
    __shared__ float red[8][32][33];
    const int wip  = threadIdx.x >> 5;             // warp in block
    const int w    = blockIdx.x * 8 + wip;
    const int lane = threadIdx.x & 31;
    const int b = w >> 8, h = w & 255;
    const int idx = h * NST + lane;
    const float rr   = g_ssm[0 * DM * NST + idx];
    const float ri   = g_ssm[1 * DM * NST + idx];
    const float c2r  = g_ssm[2 * DM * NST + idx];
    const float nc2i = -g_ssm[3 * DM * NST + idx];
    const float nri  = -ri;
    const float Dh   = Dv[h];
    const float* ue = g_ue + ((size_t)(b * DM + h)) * LIN;
    const float* uo = g_uo + ((size_t)(b * DM + h)) * LIN;
    float* op = out + ((size_t)(b * DM + h)) * LOUT;

    float xr = 0.f, xi = 0.f;
    for (int l0 = 0; l0 < LIN; l0 += 16) {
        float ge[16], go[16];
#pragma unroll
        for (int i = 0; i < 16; ++i) {
            float u0 = __ldg(&ue[l0 + i]), u1 = __ldg(&uo[l0 + i]);
            // t = 2(l0+i)
            float t0  = fmaf(nri, xi, u0);
            float xr2 = fmaf(rr, xr, t0);
            float xi2 = fmaf(rr, xi, ri * xr);
            ge[i] = fmaf(c2r, xr2, nc2i * xi2);
            // t = 2(l0+i)+1
            float t1 = fmaf(nri, xi2, u1);
            xr = fmaf(rr, xr2, t1);
            xi = fmaf(rr, xi2, ri * xr2);
            go[i] = fmaf(c2r, xr, nc2i * xi);
        }
        // transpose: lane writes its 16 even to cols 0..15, 16 odd to cols 16..31
#pragma unroll
        for (int i = 0; i < 16; ++i) {
            red[wip][lane][i]      = ge[i];
            red[wip][lane][16 + i] = go[i];
        }
        __syncwarp();
        // lane sums column `lane` over 32 states
        float s = 0.f;
#pragma unroll
        for (int j = 0; j < 32; ++j) s += red[wip][j][lane];
        // lane < 16 -> even output at l0+lane ; lane >= 16 -> odd at l0+lane-16
        int li = l0 + (lane & 15);
        float u = (lane < 16) ? __ldg(&ue[li]) : __ldg(&uo[li]);
        int t  = 2 * li + (lane >> 4);
        op[t] = fmaf(Dh, u, s);
        __syncwarp();
    }
}

extern "C" void kernel_launch(void* const* d_in, const int* in_sizes, int n_in,
                              void* d_out, int out_size) {
    (void)in_sizes; (void)n_in; (void)out_size;
    const float* x        = (const float*)d_in[0];
    const float* w1       = (const float*)d_in[1];
    const float* b1       = (const float*)d_in[2];
    const float* w2       = (const float*)d_in[3];
    const float* b2       = (const float*)d_in[4];
    const float* w3       = (const float*)d_in[5];
    const float* b3       = (const float*)d_in[6];
    const float* w4       = (const float*)d_in[7];
    const float* b4       = (const float*)d_in[8];
    const float* bn_gamma = (const float*)d_in[9];
    const float* bn_beta  = (const float*)d_in[10];
    const float* conv_w   = (const float*)d_in[11];
    const float* conv_b   = (const float*)d_in[12];
    const float* A_re     = (const float*)d_in[13];
    const float* A_im     = (const float*)d_in[14];
    const float* log_dt   = (const float*)d_in[15];
    const float* C_re     = (const float*)d_in[16];
    const float* C_im     = (const float*)d_in[17];
    const float* Dv       = (const float*)d_in[18];
    float* out = (float*)d_out;

    k_wprep<<<512, 256>>>(w1, w2, w3, w4);
    k1_deconv<<<dim3(LIN / 128, 5, BB), 256>>>(x, b1, b2, b3, b4);
    k_stats<<<CCAT, 256>>>(b2, b3, b4, bn_gamma, bn_beta);
    k_fold<<<DM, 256>>>(conv_w, conv_b, b2, b3, b4);
    k_gemm2<<<dim3(LIN / 128, DM / 128, BB), 256>>>(0);
    k_gemm2<<<dim3(LIN / 128, DM / 128, BB), 256>>>(1);
    k_s4setup<<<DM, NST>>>(A_re, A_im, log_dt, C_re, C_im);
    k_scan<<<(BB * DM) / 8, 256>>>(Dv, out);
}